// round 10
// baseline (speedup 1.0000x reference)
#include <cuda_runtime.h>
#include <cuda_fp16.h>
#include <math.h>
#include <stdint.h>

// ============================================================
// EGNN layer, factored P/Q + fp16 mma.sync m16n8k16.
// Round-10: (1) silu via tanh.approx.f32 (1 MUFU vs 2 — MUFU was
// ~half the edge kernel's cycle budget), (2) scatter red.v4 via
// shfl_xor lane pairing (half the REDG lanes), (3) double-buffered
// A tile -> one __syncthreads per edge tile.
//   pq:   P,Q = h@W1a^T, h@W1b^T  (per NODE, not per edge)
//   edge: m = silu(P[s]+Q[r]+dist*wl+b1); silu(m@W2^T+b2) scatter
//         (persistent, W2 resident in smem)
//   node: [h@U1a^T + agg@U1b^T]+c1 silu -> @U2^T +c2 + h
// ============================================================

#define DD       128
#define NMAX     50000
#define EMAX     800000
#define APITCHB  272
#define BPITCHB  144
#define BCHUNKB  (128 * BPITCHB)     // 18432
#define BCHUNKH  (BCHUNKB / 2)
#define ABYTES   (128 * APITCHB)     // 34816
#define SMEM_STREAM (ABYTES + 2 * BCHUNKB)            // 71680
#define SMEM_EDGE   (2 * BCHUNKB + 2 * ABYTES)        // 106496

__device__ __align__(16) float  g_agg[(size_t)NMAX * DD];
__device__ __align__(16) __half g_P[(size_t)NMAX * DD];
__device__ __align__(16) __half g_Q[(size_t)NMAX * DD];
__device__ __align__(16) __half g_W1a[2 * BCHUNKH];
__device__ __align__(16) __half g_W1b[2 * BCHUNKH];
__device__ __align__(16) __half g_W2i[2 * BCHUNKH];
__device__ __align__(16) __half g_U1a[2 * BCHUNKH];
__device__ __align__(16) __half g_U1b[2 * BCHUNKH];
__device__ __align__(16) __half g_U2i[2 * BCHUNKH];
__device__ __align__(16) float  g_wlast[DD];
__device__ int g_sidx[EMAX];
__device__ int g_ridx[EMAX];
__device__ int g_is64;

// ---------------- helpers ----------------
__device__ __forceinline__ uint32_t smem_u32(const void* p) {
    uint32_t a;
    asm("{ .reg .u64 t; cvta.to.shared.u64 t, %1; cvt.u32.u64 %0, t; }"
        : "=r"(a) : "l"(p));
    return a;
}
// silu(x) = x*sigmoid(x) = hx*(1+tanh(hx)), hx = x/2.  1 MUFU (TANH).
__device__ __forceinline__ float silu_f(float x) {
    float hx = 0.5f * x, t;
    asm("tanh.approx.f32 %0, %1;" : "=f"(t) : "f"(hx));
    return fmaf(hx, t, hx);
}
__device__ __forceinline__ void red_add_v4(float* p, float a, float b, float c, float d) {
    asm volatile("red.global.add.v4.f32 [%0], {%1,%2,%3,%4};"
                 :: "l"(p), "f"(a), "f"(b), "f"(c), "f"(d) : "memory");
}
__device__ __forceinline__ void cp_async16(void* dst_smem, const void* src) {
    uint32_t d = smem_u32(dst_smem);
    asm volatile("cp.async.cg.shared.global [%0], [%1], 16;" :: "r"(d), "l"(src) : "memory");
}
#define CP_COMMIT() asm volatile("cp.async.commit_group;" ::: "memory")
#define CP_WAIT0()  asm volatile("cp.async.wait_group 0;" ::: "memory")
#define CP_WAIT1()  asm volatile("cp.async.wait_group 1;" ::: "memory")

__device__ __forceinline__ void ldsm4(uint32_t& r0, uint32_t& r1, uint32_t& r2, uint32_t& r3,
                                      uint32_t addr) {
    asm volatile("ldmatrix.sync.aligned.m8n8.x4.shared.b16 {%0,%1,%2,%3}, [%4];"
                 : "=r"(r0), "=r"(r1), "=r"(r2), "=r"(r3) : "r"(addr));
}
__device__ __forceinline__ void mma_fp16(float c[4], const uint32_t a[4], const uint32_t b[2]) {
    asm volatile("mma.sync.aligned.m16n8k16.row.col.f32.f16.f16.f32 "
                 "{%0,%1,%2,%3}, {%4,%5,%6,%7}, {%8,%9}, {%0,%1,%2,%3};"
                 : "+f"(c[0]), "+f"(c[1]), "+f"(c[2]), "+f"(c[3])
                 : "r"(a[0]), "r"(a[1]), "r"(a[2]), "r"(a[3]), "r"(b[0]), "r"(b[1]));
}

// ---------------- prep kernels ----------------
__global__ void detect_kernel(const int* __restrict__ ei32) {
    if (threadIdx.x == 0) {
        int any = 0;
        #pragma unroll
        for (int i = 1; i < 64; i += 2) any |= ei32[i];
        g_is64 = (any == 0) ? 1 : 0;
    }
}
__global__ void decode_kernel(const int* __restrict__ ei32, int E) {
    int e = blockIdx.x * blockDim.x + threadIdx.x;
    if (e < E) {
        if (g_is64) { g_sidx[e] = ei32[2 * e]; g_ridx[e] = ei32[2 * E + 2 * e]; }
        else        { g_sidx[e] = ei32[e];     g_ridx[e] = ei32[E + e]; }
    }
}
__global__ void zero_agg_kernel(int n4) {
    int i = blockIdx.x * blockDim.x + threadIdx.x;
    int stride = gridDim.x * blockDim.x;
    float4* p = reinterpret_cast<float4*>(g_agg);
    float4 z = make_float4(0.f, 0.f, 0.f, 0.f);
    for (int t = i; t < n4; t += stride) p[t] = z;
}
__global__ void prep_all_kernel(const float* __restrict__ W1, const float* __restrict__ W2,
                                const float* __restrict__ U1, const float* __restrict__ U2) {
    int which = blockIdx.y;
    if (which == 6) {
        if (blockIdx.x == 0 && threadIdx.x < DD)
            g_wlast[threadIdx.x] = W1[(size_t)threadIdx.x * 257 + 256];
        return;
    }
    const float* src; __half* dst; int K_in, k_off;
    switch (which) {
        case 0: src = W1; dst = g_W1a; K_in = 257; k_off = 0;   break;
        case 1: src = W1; dst = g_W1b; K_in = 257; k_off = 128; break;
        case 2: src = W2; dst = g_W2i; K_in = 128; k_off = 0;   break;
        case 3: src = U1; dst = g_U1a; K_in = 256; k_off = 0;   break;
        case 4: src = U1; dst = g_U1b; K_in = 256; k_off = 128; break;
        default: src = U2; dst = g_U2i; K_in = 128; k_off = 0;  break;
    }
    int idx = blockIdx.x * 256 + threadIdx.x;
    int n = idx >> 7, k = idx & 127;
    int kb = k >> 6, kl = k & 63;
    dst[kb * BCHUNKH + n * (BPITCHB / 2) + kl] =
        __float2half_rn(src[(size_t)n * K_in + k_off + k]);
}

// ---------------- core pieces ----------------
__device__ __forceinline__ void load_chunk(char* dst, const __half* __restrict__ src, int tid) {
    const float4* s4 = reinterpret_cast<const float4*>(src);
    float4* d4 = reinterpret_cast<float4*>(dst);
    #pragma unroll 5
    for (int i = tid; i < BCHUNKB / 16; i += 256)
        cp_async16(d4 + i, s4 + i);
}

__device__ __forceinline__ void gather_tile(char* A, const float* __restrict__ base,
                                            const int* __restrict__ rows, int tid) {
    int row = tid >> 1, half = tid & 1;
    const float4* src = reinterpret_cast<const float4*>(base + (size_t)rows[row] * DD + half * 64);
    char* dstp = A + row * APITCHB + half * 128;
    #pragma unroll
    for (int i = 0; i < 8; ++i) {
        float4 v0 = src[2 * i], v1 = src[2 * i + 1];
        __half2 h0 = __floats2half2_rn(v0.x, v0.y);
        __half2 h1 = __floats2half2_rn(v0.z, v0.w);
        __half2 h2 = __floats2half2_rn(v1.x, v1.y);
        __half2 h3 = __floats2half2_rn(v1.z, v1.w);
        uint4 u;
        u.x = *reinterpret_cast<uint32_t*>(&h0);
        u.y = *reinterpret_cast<uint32_t*>(&h1);
        u.z = *reinterpret_cast<uint32_t*>(&h2);
        u.w = *reinterpret_cast<uint32_t*>(&h3);
        *reinterpret_cast<uint4*>(dstp + i * 16) = u;
    }
}

__device__ __forceinline__ void mma_chunk(uint32_t Ab, uint32_t Bb, int kbaseB,
                                          int wr, int wc, int lane, float acc[4][4][4]) {
    int arow = (lane & 7) + ((lane & 8) ? 8 : 0);
    int ak   = (lane & 16) ? 8 : 0;
    int bn   = (lane & 7) + ((lane & 16) ? 8 : 0);
    int bk   = (lane & 8) ? 8 : 0;
    uint32_t abase = Ab + (wr * 64 + arow) * APITCHB + kbaseB + ak * 2;
    uint32_t bbase = Bb + (wc * 32 + bn) * BPITCHB + bk * 2;
    #pragma unroll
    for (int ks = 0; ks < 4; ++ks) {
        uint32_t af[4][4];
        #pragma unroll
        for (int mt = 0; mt < 4; ++mt)
            ldsm4(af[mt][0], af[mt][1], af[mt][2], af[mt][3],
                  abase + mt * 16 * APITCHB + ks * 32);
        uint32_t bf[2][4];
        #pragma unroll
        for (int p = 0; p < 2; ++p)
            ldsm4(bf[p][0], bf[p][1], bf[p][2], bf[p][3],
                  bbase + p * 16 * BPITCHB + ks * 32);
        #pragma unroll
        for (int mt = 0; mt < 4; ++mt)
            #pragma unroll
            for (int p = 0; p < 2; ++p) {
                mma_fp16(acc[mt][2 * p],     af[mt], &bf[p][0]);
                mma_fp16(acc[mt][2 * p + 1], af[mt], &bf[p][2]);
            }
    }
}

__device__ __forceinline__ void gemm_pass(uint32_t Ab, char* B0, char* B1,
                                          const __half* __restrict__ img, int tid,
                                          int wr, int wc, int lane, float acc[4][4][4]) {
    load_chunk(B0, img, tid);           CP_COMMIT();
    load_chunk(B1, img + BCHUNKH, tid); CP_COMMIT();
    CP_WAIT1();
    __syncthreads();
    mma_chunk(Ab, smem_u32(B0), 0, wr, wc, lane, acc);
    CP_WAIT0();
    __syncthreads();
    mma_chunk(Ab, smem_u32(B1), 128, wr, wc, lane, acc);
    __syncthreads();
}

#define ZERO_ACC(acc) do {                                   \
    _Pragma("unroll")                                        \
    for (int mt = 0; mt < 4; ++mt)                           \
        _Pragma("unroll")                                    \
        for (int nt = 0; nt < 4; ++nt)                       \
            _Pragma("unroll")                                \
            for (int q = 0; q < 4; ++q) acc[mt][nt][q] = 0.f;\
} while (0)

// ---------------- pq kernel ----------------
__global__ __launch_bounds__(256, 2)
void pq_kernel(const float* __restrict__ h, int N) {
    extern __shared__ __align__(16) char smem_raw[];
    char* A  = smem_raw;
    char* B0 = smem_raw + ABYTES;
    char* B1 = B0 + BCHUNKB;
    __shared__ int s_rows[128];

    const int tid = threadIdx.x;
    const int wid = tid >> 5, lane = tid & 31;
    const int wr = wid >> 2, wc = wid & 3;
    const int gid = lane >> 2, tig = lane & 3;
    const int n0 = blockIdx.x * 128;
    const uint32_t Ab = smem_u32(A);

    if (tid < 128) s_rows[tid] = (n0 + tid < N) ? n0 + tid : 0;
    __syncthreads();

    gather_tile(A, h, s_rows, tid);
    __syncthreads();

    float acc[4][4][4];
    #pragma unroll 1
    for (int pass = 0; pass < 2; ++pass) {
        ZERO_ACC(acc);
        gemm_pass(Ab, B0, B1, pass ? g_W1b : g_W1a, tid, wr, wc, lane, acc);
        __half* dst = pass ? g_Q : g_P;
        #pragma unroll
        for (int mt = 0; mt < 4; ++mt) {
            int r0 = wr * 64 + mt * 16 + gid, r1 = r0 + 8;
            int na = n0 + r0, nb = n0 + r1;
            #pragma unroll
            for (int nt = 0; nt < 4; ++nt) {
                int c = wc * 32 + nt * 8 + 2 * tig;
                if (na < N)
                    *reinterpret_cast<__half2*>(dst + (size_t)na * DD + c) =
                        __floats2half2_rn(acc[mt][nt][0], acc[mt][nt][1]);
                if (nb < N)
                    *reinterpret_cast<__half2*>(dst + (size_t)nb * DD + c) =
                        __floats2half2_rn(acc[mt][nt][2], acc[mt][nt][3]);
            }
        }
    }
}

// ---------------- edge kernel (persistent, W2 resident, A double-buffered) ----------------
__global__ __launch_bounds__(256, 2)
void edge_kernel(const float* __restrict__ coords,
                 const float* __restrict__ b1, const float* __restrict__ b2,
                 int E, int ntiles) {
    extern __shared__ __align__(16) char smem_raw[];
    char* Wsm   = smem_raw;                      // resident W2 (2 chunks)
    char* Abase = smem_raw + 2 * BCHUNKB;        // 2 A buffers
    __shared__ int s_ridx[2][128];
    __shared__ float s_wl[128], s_b1[128], s_b2[128];

    const int tid = threadIdx.x;
    const int wid = tid >> 5, lane = tid & 31;
    const int wr = wid >> 2, wc = wid & 3;
    const int gid = lane >> 2, tig = lane & 3;
    const uint32_t Wb = smem_u32(Wsm);

    {
        const float4* s4 = reinterpret_cast<const float4*>(g_W2i);
        float4* d4 = reinterpret_cast<float4*>(Wsm);
        #pragma unroll 5
        for (int i = tid; i < 2 * BCHUNKB / 16; i += 256)
            cp_async16(d4 + i, s4 + i);
        CP_COMMIT();
        if (tid < 128) {
            s_wl[tid] = g_wlast[tid];
            s_b1[tid] = b1[tid];
            s_b2[tid] = b2[tid];
        }
        CP_WAIT0();
    }
    __syncthreads();

    const int row = tid >> 1, half = tid & 1;
    int buf = 0;

    for (int t = blockIdx.x; t < ntiles; t += gridDim.x, buf ^= 1) {
        char* A = Abase + buf * ABYTES;
        const uint32_t Ab = smem_u32(A);

        // ---- combine: A[row] = fp16(silu(P[s]+Q[r]+dist*wl+b1)) ----
        int e = t * 128 + row;
        bool valid = (e < E);
        int s = valid ? g_sidx[e] : 0;
        int r = valid ? g_ridx[e] : 0;
        if (half == 0) s_ridx[buf][row] = r;
        float dx = coords[3 * s]     - coords[3 * r];
        float dy = coords[3 * s + 1] - coords[3 * r + 1];
        float dz = coords[3 * s + 2] - coords[3 * r + 2];
        float dist = sqrtf(dx * dx + dy * dy + dz * dz);

        const uint4* Pp = reinterpret_cast<const uint4*>(g_P + (size_t)s * DD + half * 64);
        const uint4* Qp = reinterpret_cast<const uint4*>(g_Q + (size_t)r * DD + half * 64);
        char* dstp = A + row * APITCHB + half * 128;
        #pragma unroll
        for (int i = 0; i < 8; ++i) {
            uint4 pu = Pp[i], qu = Qp[i];
            const __half2* ph = reinterpret_cast<const __half2*>(&pu);
            const __half2* qh = reinterpret_cast<const __half2*>(&qu);
            uint4 o;
            uint32_t* ow = reinterpret_cast<uint32_t*>(&o);
            #pragma unroll
            for (int j = 0; j < 4; ++j) {
                int c = half * 64 + i * 8 + j * 2;
                float2 pf = __half22float2(ph[j]);
                float2 qf = __half22float2(qh[j]);
                float x0 = silu_f(pf.x + qf.x + dist * s_wl[c]     + s_b1[c]);
                float x1 = silu_f(pf.y + qf.y + dist * s_wl[c + 1] + s_b1[c + 1]);
                __half2 hh = __floats2half2_rn(x0, x1);
                ow[j] = *reinterpret_cast<uint32_t*>(&hh);
            }
            *reinterpret_cast<uint4*>(dstp + i * 16) = o;
        }
        __syncthreads();      // only sync per tile (A buffers alternate)

        // ---- layer 2: m@W2^T (resident) ----
        float acc[4][4][4];
        ZERO_ACC(acc);
        mma_chunk(Ab, Wb, 0, wr, wc, lane, acc);
        mma_chunk(Ab, Wb + BCHUNKB, 128, wr, wc, lane, acc);

        // ---- epilogue: silu(acc+b2) -> pairwise shfl -> red.v4 scatter ----
        int e0 = t * 128;
        #pragma unroll
        for (int mt = 0; mt < 4; ++mt) {
            int r0 = wr * 64 + mt * 16 + gid, r1 = r0 + 8;
            bool v0 = (e0 + r0 < E), v1 = (e0 + r1 < E);
            float* d0p = g_agg + (size_t)s_ridx[buf][r0] * DD;
            float* d1p = g_agg + (size_t)s_ridx[buf][r1] * DD;
            #pragma unroll
            for (int nt = 0; nt < 4; ++nt) {
                int c = wc * 32 + nt * 8 + 2 * tig;
                float s0 = silu_f(acc[mt][nt][0] + s_b2[c]);
                float s1 = silu_f(acc[mt][nt][1] + s_b2[c + 1]);
                float s2 = silu_f(acc[mt][nt][2] + s_b2[c]);
                float s3 = silu_f(acc[mt][nt][3] + s_b2[c + 1]);
                float n0 = __shfl_xor_sync(0xffffffffu, s0, 1);
                float n1 = __shfl_xor_sync(0xffffffffu, s1, 1);
                float n2 = __shfl_xor_sync(0xffffffffu, s2, 1);
                float n3 = __shfl_xor_sync(0xffffffffu, s3, 1);
                if (!(tig & 1)) {
                    if (v0) red_add_v4(d0p + c, s0, s1, n0, n1);
                    if (v1) red_add_v4(d1p + c, s2, s3, n2, n3);
                }
            }
        }
        // no trailing sync: next combine writes the other A buffer / s_ridx slot
    }
}

// ---------------- node kernel ----------------
__global__ __launch_bounds__(256, 2)
void node_kernel(const float* __restrict__ h,
                 const float* __restrict__ c1, const float* __restrict__ c2,
                 float* __restrict__ out, int N) {
    extern __shared__ __align__(16) char smem_raw[];
    char* A  = smem_raw;
    char* B0 = smem_raw + ABYTES;
    char* B1 = B0 + BCHUNKB;
    __shared__ int s_rows[128];

    const int tid = threadIdx.x;
    const int wid = tid >> 5, lane = tid & 31;
    const int wr = wid >> 2, wc = wid & 3;
    const int gid = lane >> 2, tig = lane & 3;
    const int n0 = blockIdx.x * 128;
    const uint32_t Ab = smem_u32(A);

    if (tid < 128) s_rows[tid] = (n0 + tid < N) ? n0 + tid : 0;
    __syncthreads();

    float acc[4][4][4];
    ZERO_ACC(acc);

    gather_tile(A, h, s_rows, tid);
    __syncthreads();
    gemm_pass(Ab, B0, B1, g_U1a, tid, wr, wc, lane, acc);
    gather_tile(A, g_agg, s_rows, tid);
    __syncthreads();
    gemm_pass(Ab, B0, B1, g_U1b, tid, wr, wc, lane, acc);

    #pragma unroll
    for (int mt = 0; mt < 4; ++mt) {
        int r0 = wr * 64 + mt * 16 + gid, r1 = r0 + 8;
        #pragma unroll
        for (int nt = 0; nt < 4; ++nt) {
            int c = wc * 32 + nt * 8 + 2 * tig;
            float bb0 = c1[c], bb1 = c1[c + 1];
            __half2 m0 = __floats2half2_rn(silu_f(acc[mt][nt][0] + bb0),
                                           silu_f(acc[mt][nt][1] + bb1));
            __half2 m1 = __floats2half2_rn(silu_f(acc[mt][nt][2] + bb0),
                                           silu_f(acc[mt][nt][3] + bb1));
            *reinterpret_cast<__half2*>(A + r0 * APITCHB + c * 2) = m0;
            *reinterpret_cast<__half2*>(A + r1 * APITCHB + c * 2) = m1;
            acc[mt][nt][0] = acc[mt][nt][1] = acc[mt][nt][2] = acc[mt][nt][3] = 0.f;
        }
    }
    __syncthreads();

    gemm_pass(Ab, B0, B1, g_U2i, tid, wr, wc, lane, acc);

    #pragma unroll
    for (int mt = 0; mt < 4; ++mt) {
        int r0 = wr * 64 + mt * 16 + gid, r1 = r0 + 8;
        int na = n0 + r0, nb = n0 + r1;
        #pragma unroll
        for (int nt = 0; nt < 4; ++nt) {
            int c = wc * 32 + nt * 8 + 2 * tig;
            float bb0 = c2[c], bb1 = c2[c + 1];
            if (na < N) {
                const float2 hv = *reinterpret_cast<const float2*>(h + (size_t)na * DD + c);
                float2 o;
                o.x = hv.x + acc[mt][nt][0] + bb0;
                o.y = hv.y + acc[mt][nt][1] + bb1;
                *reinterpret_cast<float2*>(out + (size_t)na * DD + c) = o;
            }
            if (nb < N) {
                const float2 hv = *reinterpret_cast<const float2*>(h + (size_t)nb * DD + c);
                float2 o;
                o.x = hv.x + acc[mt][nt][2] + bb0;
                o.y = hv.y + acc[mt][nt][3] + bb1;
                *reinterpret_cast<float2*>(out + (size_t)nb * DD + c) = o;
            }
        }
    }
}

// ---------------- launch ----------------
extern "C" void kernel_launch(void* const* d_in, const int* in_sizes, int n_in,
                              void* d_out, int out_size) {
    const float* h      = (const float*)d_in[0];
    const float* coords = (const float*)d_in[1];
    const int*   ei32   = (const int*)d_in[2];
    const float* W1     = (const float*)d_in[3];
    const float* b1     = (const float*)d_in[4];
    const float* W2     = (const float*)d_in[5];
    const float* b2     = (const float*)d_in[6];
    const float* U1     = (const float*)d_in[7];
    const float* c1     = (const float*)d_in[8];
    const float* U2     = (const float*)d_in[9];
    const float* c2     = (const float*)d_in[10];
    float* out = (float*)d_out;

    const int N = in_sizes[0] / DD;
    const int E = in_sizes[2] / 2;
    const int etiles = (E + 127) / 128;
    const int vtiles = (N + 127) / 128;

    cudaFuncSetAttribute(pq_kernel,   cudaFuncAttributeMaxDynamicSharedMemorySize, SMEM_STREAM);
    cudaFuncSetAttribute(edge_kernel, cudaFuncAttributeMaxDynamicSharedMemorySize, SMEM_EDGE);
    cudaFuncSetAttribute(node_kernel, cudaFuncAttributeMaxDynamicSharedMemorySize, SMEM_STREAM);

    detect_kernel<<<1, 32>>>(ei32);
    decode_kernel<<<(E + 255) / 256, 256>>>(ei32, E);
    zero_agg_kernel<<<512, 256>>>(N * DD / 4);
    prep_all_kernel<<<dim3(64, 7), 256>>>(W1, W2, U1, U2);

    pq_kernel<<<vtiles, 256, SMEM_STREAM>>>(h, N);
    edge_kernel<<<296, 256, SMEM_EDGE>>>(coords, b1, b2, E, etiles);
    node_kernel<<<vtiles, 256, SMEM_STREAM>>>(h, c1, c2, out, N);
}

// round 11
// speedup vs baseline: 1.5541x; 1.5541x over previous
#include <cuda_runtime.h>
#include <cuda_fp16.h>
#include <math.h>
#include <stdint.h>

// ============================================================
// EGNN layer, factored P/Q + fp16 mma.sync m16n8k16.
// EXACT round-9 structure (372us proven) with ONE change:
// silu via tanh.approx.f32 (1 MUFU) instead of exp+div (2 MUFU).
//   pq:   P,Q = h@W1a^T, h@W1b^T  (per NODE, not per edge)
//   edge: m = silu(P[s]+Q[r]+dist*wl+b1); silu(m@W2^T+b2) scatter
//         (persistent, W2 resident in smem, single A buffer, 2 syncs)
//   node: [h@U1a^T + agg@U1b^T]+c1 silu -> @U2^T +c2 + h
// ============================================================

#define DD       128
#define NMAX     50000
#define EMAX     800000
#define APITCHB  272
#define BPITCHB  144
#define BCHUNKB  (128 * BPITCHB)     // 18432
#define BCHUNKH  (BCHUNKB / 2)
#define ABYTES   (128 * APITCHB)     // 34816
#define SMEM_STREAM (ABYTES + 2 * BCHUNKB)   // 71680
#define SMEM_EDGE   (2 * BCHUNKB + ABYTES)   // 71680

__device__ __align__(16) float  g_agg[(size_t)NMAX * DD];
__device__ __align__(16) __half g_P[(size_t)NMAX * DD];
__device__ __align__(16) __half g_Q[(size_t)NMAX * DD];
__device__ __align__(16) __half g_W1a[2 * BCHUNKH];
__device__ __align__(16) __half g_W1b[2 * BCHUNKH];
__device__ __align__(16) __half g_W2i[2 * BCHUNKH];
__device__ __align__(16) __half g_U1a[2 * BCHUNKH];
__device__ __align__(16) __half g_U1b[2 * BCHUNKH];
__device__ __align__(16) __half g_U2i[2 * BCHUNKH];
__device__ __align__(16) float  g_wlast[DD];
__device__ int g_sidx[EMAX];
__device__ int g_ridx[EMAX];
__device__ int g_is64;

// ---------------- helpers ----------------
__device__ __forceinline__ uint32_t smem_u32(const void* p) {
    uint32_t a;
    asm("{ .reg .u64 t; cvta.to.shared.u64 t, %1; cvt.u32.u64 %0, t; }"
        : "=r"(a) : "l"(p));
    return a;
}
// silu(x) = x*sigmoid(x) = hx + hx*tanh(hx), hx = x/2.  1 MUFU.
__device__ __forceinline__ float silu_f(float x) {
    float hx = 0.5f * x, t;
    asm("tanh.approx.f32 %0, %1;" : "=f"(t) : "f"(hx));
    return fmaf(hx, t, hx);
}
__device__ __forceinline__ void red_add_v2(float* p, float a, float b) {
    asm volatile("red.global.add.v2.f32 [%0], {%1,%2};"
                 :: "l"(p), "f"(a), "f"(b) : "memory");
}
__device__ __forceinline__ void cp_async16(void* dst_smem, const void* src) {
    uint32_t d = smem_u32(dst_smem);
    asm volatile("cp.async.cg.shared.global [%0], [%1], 16;" :: "r"(d), "l"(src) : "memory");
}
#define CP_COMMIT() asm volatile("cp.async.commit_group;" ::: "memory")
#define CP_WAIT0()  asm volatile("cp.async.wait_group 0;" ::: "memory")
#define CP_WAIT1()  asm volatile("cp.async.wait_group 1;" ::: "memory")

__device__ __forceinline__ void ldsm4(uint32_t& r0, uint32_t& r1, uint32_t& r2, uint32_t& r3,
                                      uint32_t addr) {
    asm volatile("ldmatrix.sync.aligned.m8n8.x4.shared.b16 {%0,%1,%2,%3}, [%4];"
                 : "=r"(r0), "=r"(r1), "=r"(r2), "=r"(r3) : "r"(addr));
}
__device__ __forceinline__ void mma_fp16(float c[4], const uint32_t a[4], const uint32_t b[2]) {
    asm volatile("mma.sync.aligned.m16n8k16.row.col.f32.f16.f16.f32 "
                 "{%0,%1,%2,%3}, {%4,%5,%6,%7}, {%8,%9}, {%0,%1,%2,%3};"
                 : "+f"(c[0]), "+f"(c[1]), "+f"(c[2]), "+f"(c[3])
                 : "r"(a[0]), "r"(a[1]), "r"(a[2]), "r"(a[3]), "r"(b[0]), "r"(b[1]));
}

// ---------------- prep kernels ----------------
__global__ void detect_kernel(const int* __restrict__ ei32) {
    if (threadIdx.x == 0) {
        int any = 0;
        #pragma unroll
        for (int i = 1; i < 64; i += 2) any |= ei32[i];
        g_is64 = (any == 0) ? 1 : 0;
    }
}
__global__ void decode_kernel(const int* __restrict__ ei32, int E) {
    int e = blockIdx.x * blockDim.x + threadIdx.x;
    if (e < E) {
        if (g_is64) { g_sidx[e] = ei32[2 * e]; g_ridx[e] = ei32[2 * E + 2 * e]; }
        else        { g_sidx[e] = ei32[e];     g_ridx[e] = ei32[E + e]; }
    }
}
__global__ void zero_agg_kernel(int n4) {
    int i = blockIdx.x * blockDim.x + threadIdx.x;
    int stride = gridDim.x * blockDim.x;
    float4* p = reinterpret_cast<float4*>(g_agg);
    float4 z = make_float4(0.f, 0.f, 0.f, 0.f);
    for (int t = i; t < n4; t += stride) p[t] = z;
}
__global__ void prep_all_kernel(const float* __restrict__ W1, const float* __restrict__ W2,
                                const float* __restrict__ U1, const float* __restrict__ U2) {
    int which = blockIdx.y;
    if (which == 6) {
        if (blockIdx.x == 0 && threadIdx.x < DD)
            g_wlast[threadIdx.x] = W1[(size_t)threadIdx.x * 257 + 256];
        return;
    }
    const float* src; __half* dst; int K_in, k_off;
    switch (which) {
        case 0: src = W1; dst = g_W1a; K_in = 257; k_off = 0;   break;
        case 1: src = W1; dst = g_W1b; K_in = 257; k_off = 128; break;
        case 2: src = W2; dst = g_W2i; K_in = 128; k_off = 0;   break;
        case 3: src = U1; dst = g_U1a; K_in = 256; k_off = 0;   break;
        case 4: src = U1; dst = g_U1b; K_in = 256; k_off = 128; break;
        default: src = U2; dst = g_U2i; K_in = 128; k_off = 0;  break;
    }
    int idx = blockIdx.x * 256 + threadIdx.x;
    int n = idx >> 7, k = idx & 127;
    int kb = k >> 6, kl = k & 63;
    dst[kb * BCHUNKH + n * (BPITCHB / 2) + kl] =
        __float2half_rn(src[(size_t)n * K_in + k_off + k]);
}

// ---------------- core pieces ----------------
__device__ __forceinline__ void load_chunk(char* dst, const __half* __restrict__ src, int tid) {
    const float4* s4 = reinterpret_cast<const float4*>(src);
    float4* d4 = reinterpret_cast<float4*>(dst);
    #pragma unroll 5
    for (int i = tid; i < BCHUNKB / 16; i += 256)
        cp_async16(d4 + i, s4 + i);
}

// gather fp32 rows -> fp16 A tile; row index via array
__device__ __forceinline__ void gather_tile(char* A, const float* __restrict__ base,
                                            const int* __restrict__ rows, int tid) {
    int row = tid >> 1, half = tid & 1;
    const float4* src = reinterpret_cast<const float4*>(base + (size_t)rows[row] * DD + half * 64);
    char* dstp = A + row * APITCHB + half * 128;
    #pragma unroll
    for (int i = 0; i < 8; ++i) {
        float4 v0 = src[2 * i], v1 = src[2 * i + 1];
        __half2 h0 = __floats2half2_rn(v0.x, v0.y);
        __half2 h1 = __floats2half2_rn(v0.z, v0.w);
        __half2 h2 = __floats2half2_rn(v1.x, v1.y);
        __half2 h3 = __floats2half2_rn(v1.z, v1.w);
        uint4 u;
        u.x = *reinterpret_cast<uint32_t*>(&h0);
        u.y = *reinterpret_cast<uint32_t*>(&h1);
        u.z = *reinterpret_cast<uint32_t*>(&h2);
        u.w = *reinterpret_cast<uint32_t*>(&h3);
        *reinterpret_cast<uint4*>(dstp + i * 16) = u;
    }
}

__device__ __forceinline__ void mma_chunk(uint32_t Ab, uint32_t Bb, int kbaseB,
                                          int wr, int wc, int lane, float acc[4][4][4]) {
    int arow = (lane & 7) + ((lane & 8) ? 8 : 0);
    int ak   = (lane & 16) ? 8 : 0;
    int bn   = (lane & 7) + ((lane & 16) ? 8 : 0);
    int bk   = (lane & 8) ? 8 : 0;
    uint32_t abase = Ab + (wr * 64 + arow) * APITCHB + kbaseB + ak * 2;
    uint32_t bbase = Bb + (wc * 32 + bn) * BPITCHB + bk * 2;
    #pragma unroll
    for (int ks = 0; ks < 4; ++ks) {
        uint32_t af[4][4];
        #pragma unroll
        for (int mt = 0; mt < 4; ++mt)
            ldsm4(af[mt][0], af[mt][1], af[mt][2], af[mt][3],
                  abase + mt * 16 * APITCHB + ks * 32);
        uint32_t bf[2][4];
        #pragma unroll
        for (int p = 0; p < 2; ++p)
            ldsm4(bf[p][0], bf[p][1], bf[p][2], bf[p][3],
                  bbase + p * 16 * BPITCHB + ks * 32);
        #pragma unroll
        for (int mt = 0; mt < 4; ++mt)
            #pragma unroll
            for (int p = 0; p < 2; ++p) {
                mma_fp16(acc[mt][2 * p],     af[mt], &bf[p][0]);
                mma_fp16(acc[mt][2 * p + 1], af[mt], &bf[p][2]);
            }
    }
}

__device__ __forceinline__ void gemm_pass(uint32_t Ab, char* B0, char* B1,
                                          const __half* __restrict__ img, int tid,
                                          int wr, int wc, int lane, float acc[4][4][4]) {
    load_chunk(B0, img, tid);           CP_COMMIT();
    load_chunk(B1, img + BCHUNKH, tid); CP_COMMIT();
    CP_WAIT1();
    __syncthreads();
    mma_chunk(Ab, smem_u32(B0), 0, wr, wc, lane, acc);
    CP_WAIT0();
    __syncthreads();
    mma_chunk(Ab, smem_u32(B1), 128, wr, wc, lane, acc);
    __syncthreads();
}

#define ZERO_ACC(acc) do {                                   \
    _Pragma("unroll")                                        \
    for (int mt = 0; mt < 4; ++mt)                           \
        _Pragma("unroll")                                    \
        for (int nt = 0; nt < 4; ++nt)                       \
            _Pragma("unroll")                                \
            for (int q = 0; q < 4; ++q) acc[mt][nt][q] = 0.f;\
} while (0)

// ---------------- pq kernel: P = h@W1a^T, Q = h@W1b^T ----------------
__global__ __launch_bounds__(256, 2)
void pq_kernel(const float* __restrict__ h, int N) {
    extern __shared__ __align__(16) char smem_raw[];
    char* A  = smem_raw;
    char* B0 = smem_raw + ABYTES;
    char* B1 = B0 + BCHUNKB;
    __shared__ int s_rows[128];

    const int tid = threadIdx.x;
    const int wid = tid >> 5, lane = tid & 31;
    const int wr = wid >> 2, wc = wid & 3;
    const int gid = lane >> 2, tig = lane & 3;
    const int n0 = blockIdx.x * 128;
    const uint32_t Ab = smem_u32(A);

    if (tid < 128) s_rows[tid] = (n0 + tid < N) ? n0 + tid : 0;
    __syncthreads();

    gather_tile(A, h, s_rows, tid);
    __syncthreads();

    float acc[4][4][4];
    #pragma unroll 1
    for (int pass = 0; pass < 2; ++pass) {
        ZERO_ACC(acc);
        gemm_pass(Ab, B0, B1, pass ? g_W1b : g_W1a, tid, wr, wc, lane, acc);
        __half* dst = pass ? g_Q : g_P;
        #pragma unroll
        for (int mt = 0; mt < 4; ++mt) {
            int r0 = wr * 64 + mt * 16 + gid, r1 = r0 + 8;
            int na = n0 + r0, nb = n0 + r1;
            #pragma unroll
            for (int nt = 0; nt < 4; ++nt) {
                int c = wc * 32 + nt * 8 + 2 * tig;
                if (na < N)
                    *reinterpret_cast<__half2*>(dst + (size_t)na * DD + c) =
                        __floats2half2_rn(acc[mt][nt][0], acc[mt][nt][1]);
                if (nb < N)
                    *reinterpret_cast<__half2*>(dst + (size_t)nb * DD + c) =
                        __floats2half2_rn(acc[mt][nt][2], acc[mt][nt][3]);
            }
        }
    }
}

// ---------------- edge kernel (persistent, W2 resident) ----------------
__global__ __launch_bounds__(256, 2)
void edge_kernel(const float* __restrict__ coords,
                 const float* __restrict__ b1, const float* __restrict__ b2,
                 int E, int ntiles) {
    extern __shared__ __align__(16) char smem_raw[];
    char* Wsm = smem_raw;                    // 2 chunks of W2, resident
    char* A   = smem_raw + 2 * BCHUNKB;
    __shared__ int s_ridx[128];
    __shared__ float s_wl[128], s_b1[128], s_b2[128];

    const int tid = threadIdx.x;
    const int wid = tid >> 5, lane = tid & 31;
    const int wr = wid >> 2, wc = wid & 3;
    const int gid = lane >> 2, tig = lane & 3;
    const uint32_t Ab = smem_u32(A);
    const uint32_t Wb = smem_u32(Wsm);

    // stage W2 + epilogue constants once
    {
        const float4* s4 = reinterpret_cast<const float4*>(g_W2i);
        float4* d4 = reinterpret_cast<float4*>(Wsm);
        #pragma unroll 5
        for (int i = tid; i < 2 * BCHUNKB / 16; i += 256)
            cp_async16(d4 + i, s4 + i);
        CP_COMMIT();
        if (tid < 128) {
            s_wl[tid] = g_wlast[tid];
            s_b1[tid] = b1[tid];
            s_b2[tid] = b2[tid];
        }
        CP_WAIT0();
    }
    __syncthreads();

    const int row = tid >> 1, half = tid & 1;

    for (int t = blockIdx.x; t < ntiles; t += gridDim.x) {
        // ---- combine: A[row] = fp16(silu(P[s]+Q[r]+dist*wl+b1)) ----
        int e = t * 128 + row;
        bool valid = (e < E);
        int s = valid ? g_sidx[e] : 0;
        int r = valid ? g_ridx[e] : 0;
        if (half == 0) s_ridx[row] = r;
        float dx = coords[3 * s]     - coords[3 * r];
        float dy = coords[3 * s + 1] - coords[3 * r + 1];
        float dz = coords[3 * s + 2] - coords[3 * r + 2];
        float dist = sqrtf(dx * dx + dy * dy + dz * dz);

        const uint4* Pp = reinterpret_cast<const uint4*>(g_P + (size_t)s * DD + half * 64);
        const uint4* Qp = reinterpret_cast<const uint4*>(g_Q + (size_t)r * DD + half * 64);
        char* dstp = A + row * APITCHB + half * 128;
        #pragma unroll
        for (int i = 0; i < 8; ++i) {
            uint4 pu = Pp[i], qu = Qp[i];
            const __half2* ph = reinterpret_cast<const __half2*>(&pu);
            const __half2* qh = reinterpret_cast<const __half2*>(&qu);
            uint4 o;
            uint32_t* ow = reinterpret_cast<uint32_t*>(&o);
            #pragma unroll
            for (int j = 0; j < 4; ++j) {
                int c = half * 64 + i * 8 + j * 2;
                float2 pf = __half22float2(ph[j]);
                float2 qf = __half22float2(qh[j]);
                float x0 = silu_f(pf.x + qf.x + dist * s_wl[c]     + s_b1[c]);
                float x1 = silu_f(pf.y + qf.y + dist * s_wl[c + 1] + s_b1[c + 1]);
                __half2 hh = __floats2half2_rn(x0, x1);
                ow[j] = *reinterpret_cast<uint32_t*>(&hh);
            }
            *reinterpret_cast<uint4*>(dstp + i * 16) = o;
        }
        __syncthreads();

        // ---- layer 2: m@W2^T (resident weights) ----
        float acc[4][4][4];
        ZERO_ACC(acc);
        mma_chunk(Ab, Wb, 0, wr, wc, lane, acc);
        mma_chunk(Ab, Wb + BCHUNKB, 128, wr, wc, lane, acc);

        // ---- epilogue: silu(acc + b2) -> red.v2 scatter ----
        int e0 = t * 128;
        #pragma unroll
        for (int mt = 0; mt < 4; ++mt) {
            int r0 = wr * 64 + mt * 16 + gid, r1 = r0 + 8;
            bool v0 = (e0 + r0 < E), v1 = (e0 + r1 < E);
            float* d0p = g_agg + (size_t)s_ridx[r0] * DD;
            float* d1p = g_agg + (size_t)s_ridx[r1] * DD;
            #pragma unroll
            for (int nt = 0; nt < 4; ++nt) {
                int c = wc * 32 + nt * 8 + 2 * tig;
                float bb0 = s_b2[c], bb1 = s_b2[c + 1];
                if (v0) red_add_v2(d0p + c, silu_f(acc[mt][nt][0] + bb0),
                                            silu_f(acc[mt][nt][1] + bb1));
                if (v1) red_add_v2(d1p + c, silu_f(acc[mt][nt][2] + bb0),
                                            silu_f(acc[mt][nt][3] + bb1));
            }
        }
        __syncthreads();
    }
}

// ---------------- node kernel ----------------
__global__ __launch_bounds__(256, 2)
void node_kernel(const float* __restrict__ h,
                 const float* __restrict__ c1, const float* __restrict__ c2,
                 float* __restrict__ out, int N) {
    extern __shared__ __align__(16) char smem_raw[];
    char* A  = smem_raw;
    char* B0 = smem_raw + ABYTES;
    char* B1 = B0 + BCHUNKB;
    __shared__ int s_rows[128];

    const int tid = threadIdx.x;
    const int wid = tid >> 5, lane = tid & 31;
    const int wr = wid >> 2, wc = wid & 3;
    const int gid = lane >> 2, tig = lane & 3;
    const int n0 = blockIdx.x * 128;
    const uint32_t Ab = smem_u32(A);

    if (tid < 128) s_rows[tid] = (n0 + tid < N) ? n0 + tid : 0;
    __syncthreads();

    float acc[4][4][4];
    ZERO_ACC(acc);

    gather_tile(A, h, s_rows, tid);
    __syncthreads();
    gemm_pass(Ab, B0, B1, g_U1a, tid, wr, wc, lane, acc);
    gather_tile(A, g_agg, s_rows, tid);
    __syncthreads();
    gemm_pass(Ab, B0, B1, g_U1b, tid, wr, wc, lane, acc);

    #pragma unroll
    for (int mt = 0; mt < 4; ++mt) {
        int r0 = wr * 64 + mt * 16 + gid, r1 = r0 + 8;
        #pragma unroll
        for (int nt = 0; nt < 4; ++nt) {
            int c = wc * 32 + nt * 8 + 2 * tig;
            float bb0 = c1[c], bb1 = c1[c + 1];
            __half2 m0 = __floats2half2_rn(silu_f(acc[mt][nt][0] + bb0),
                                           silu_f(acc[mt][nt][1] + bb1));
            __half2 m1 = __floats2half2_rn(silu_f(acc[mt][nt][2] + bb0),
                                           silu_f(acc[mt][nt][3] + bb1));
            *reinterpret_cast<__half2*>(A + r0 * APITCHB + c * 2) = m0;
            *reinterpret_cast<__half2*>(A + r1 * APITCHB + c * 2) = m1;
            acc[mt][nt][0] = acc[mt][nt][1] = acc[mt][nt][2] = acc[mt][nt][3] = 0.f;
        }
    }
    __syncthreads();

    gemm_pass(Ab, B0, B1, g_U2i, tid, wr, wc, lane, acc);

    #pragma unroll
    for (int mt = 0; mt < 4; ++mt) {
        int r0 = wr * 64 + mt * 16 + gid, r1 = r0 + 8;
        int na = n0 + r0, nb = n0 + r1;
        #pragma unroll
        for (int nt = 0; nt < 4; ++nt) {
            int c = wc * 32 + nt * 8 + 2 * tig;
            float bb0 = c2[c], bb1 = c2[c + 1];
            if (na < N) {
                const float2 hv = *reinterpret_cast<const float2*>(h + (size_t)na * DD + c);
                float2 o;
                o.x = hv.x + acc[mt][nt][0] + bb0;
                o.y = hv.y + acc[mt][nt][1] + bb1;
                *reinterpret_cast<float2*>(out + (size_t)na * DD + c) = o;
            }
            if (nb < N) {
                const float2 hv = *reinterpret_cast<const float2*>(h + (size_t)nb * DD + c);
                float2 o;
                o.x = hv.x + acc[mt][nt][2] + bb0;
                o.y = hv.y + acc[mt][nt][3] + bb1;
                *reinterpret_cast<float2*>(out + (size_t)nb * DD + c) = o;
            }
        }
    }
}

// ---------------- launch ----------------
extern "C" void kernel_launch(void* const* d_in, const int* in_sizes, int n_in,
                              void* d_out, int out_size) {
    const float* h      = (const float*)d_in[0];
    const float* coords = (const float*)d_in[1];
    const int*   ei32   = (const int*)d_in[2];
    const float* W1     = (const float*)d_in[3];
    const float* b1     = (const float*)d_in[4];
    const float* W2     = (const float*)d_in[5];
    const float* b2     = (const float*)d_in[6];
    const float* U1     = (const float*)d_in[7];
    const float* c1     = (const float*)d_in[8];
    const float* U2     = (const float*)d_in[9];
    const float* c2     = (const float*)d_in[10];
    float* out = (float*)d_out;

    const int N = in_sizes[0] / DD;
    const int E = in_sizes[2] / 2;
    const int etiles = (E + 127) / 128;
    const int vtiles = (N + 127) / 128;

    cudaFuncSetAttribute(pq_kernel,   cudaFuncAttributeMaxDynamicSharedMemorySize, SMEM_STREAM);
    cudaFuncSetAttribute(edge_kernel, cudaFuncAttributeMaxDynamicSharedMemorySize, SMEM_EDGE);
    cudaFuncSetAttribute(node_kernel, cudaFuncAttributeMaxDynamicSharedMemorySize, SMEM_STREAM);

    detect_kernel<<<1, 32>>>(ei32);
    decode_kernel<<<(E + 255) / 256, 256>>>(ei32, E);
    zero_agg_kernel<<<512, 256>>>(N * DD / 4);
    prep_all_kernel<<<dim3(64, 7), 256>>>(W1, W2, U1, U2);

    pq_kernel<<<vtiles, 256, SMEM_STREAM>>>(h, N);
    edge_kernel<<<296, 256, SMEM_EDGE>>>(coords, b1, b2, E, etiles);
    node_kernel<<<vtiles, 256, SMEM_STREAM>>>(h, c1, c2, out, N);
}